// round 10
// baseline (speedup 1.0000x reference)
#include <cuda_runtime.h>
#include <cuda_fp16.h>
#include <math.h>
#include <stdint.h>

#define BB 4
#define CC 256
#define HW 4096
#define K9 9
#define KK 2304   // 256*9
#define NG 32
#define CPG 8
#define NCHB 144  // KK/16 k-blocks

// ---------------- static scratch ----------------
__device__ __align__(16) __half g_cols[(size_t)8 * KK * HW];   // fp16 cols, [bb][kk][m], bb<4=cls, >=4=reg
__device__ float g_raw[(size_t)8 * CC * HW];                   // GEMM outputs (slot 0..3 reused by conv1)
__device__ __align__(16) __half g_wT1[KK * 256];               // [kk][o]
__device__ __align__(16) __half g_wTc[KK * 256];
__device__ __align__(16) __half g_wTr[KK * 256];
__device__ float g_statS[384];                                 // atomic GN sums: [0..127] conv1, [128..383] merged
__device__ float g_statQ[384];
__device__ float g_mu[384];
__device__ float g_rstd[384];

// ---------------- streams / events ----------------
struct StreamHolder {
    cudaStream_t s1;
    cudaEvent_t eF, eT;
    StreamHolder() {
        if (cudaStreamCreateWithFlags(&s1, cudaStreamNonBlocking) != cudaSuccess) s1 = 0;
        cudaEventCreateWithFlags(&eF, cudaEventDisableTiming);
        cudaEventCreateWithFlags(&eT, cudaEventDisableTiming);
    }
};
static StreamHolder g_sh;

// ---------------- helpers ----------------
__device__ __forceinline__ uint32_t smem_u32(const void* p) {
    uint32_t a;
    asm("{ .reg .u64 t; cvta.to.shared.u64 t, %1; cvt.u32.u64 %0, t; }"
        : "=r"(a) : "l"(p));
    return a;
}
__device__ __forceinline__ void cp16(uint32_t dst, const void* src) {
    asm volatile("cp.async.cg.shared.global [%0], [%1], 16;"
                 :: "r"(dst), "l"(src) : "memory");
}
__device__ __forceinline__ void cp_commit() {
    asm volatile("cp.async.commit_group;" ::: "memory");
}
__device__ __forceinline__ void cp_wait2() {
    asm volatile("cp.async.wait_group 2;" ::: "memory");
}
__device__ __forceinline__ void ldsm4t(uint32_t* d, uint32_t addr) {
    asm volatile("ldmatrix.sync.aligned.m8n8.x4.trans.shared.b16 {%0,%1,%2,%3}, [%4];"
        : "=r"(d[0]), "=r"(d[1]), "=r"(d[2]), "=r"(d[3]) : "r"(addr));
}
__device__ __forceinline__ void mma16816(float* d, const uint32_t* a,
                                         uint32_t b0, uint32_t b1) {
    asm volatile(
        "mma.sync.aligned.m16n8k16.row.col.f32.f16.f16.f32 "
        "{%0,%1,%2,%3},{%4,%5,%6,%7},{%8,%9},{%0,%1,%2,%3};"
        : "+f"(d[0]), "+f"(d[1]), "+f"(d[2]), "+f"(d[3])
        : "r"(a[0]), "r"(a[1]), "r"(a[2]), "r"(a[3]), "r"(b0), "r"(b1));
}

// ---------------- zero stat accumulators ----------------
__global__ void zero_stats() {
    int t = threadIdx.x;
    if (t < 384) { g_statS[t] = 0.f; g_statQ[t] = 0.f; }
}

// ---------------- weight transpose -> fp16: wT[kk][o] ----------------------
__global__ void transpose_all_h(const float* __restrict__ w1, const float* __restrict__ wc,
                                const float* __restrict__ wr,
                                __half* __restrict__ o1, __half* __restrict__ oc,
                                __half* __restrict__ orr) {
    const int S = KK * 256;
    int i = blockIdx.x * 256 + threadIdx.x;
    const float* w; __half* o; int j;
    if (i < S)          { w = w1; o = o1;  j = i; }
    else if (i < 2 * S) { w = wc; o = oc;  j = i - S; }
    else                { w = wr; o = orr; j = i - 2 * S; }
    int oo = j & 255;
    int kk = j >> 8;
    int ci = kk & 255;
    int tap = kk >> 8;
    o[j] = __float2half_rn(w[(oo * CC + ci) * K9 + tap]);
}

// ---------------- im2col 3x3 pad1 -> fp16 cols[b][kk][m], 2 m per thread ----
__global__ void im2col_h(const float* __restrict__ in, __half* __restrict__ cols) {
    int idx = blockIdx.x * 256 + threadIdx.x;     // BB*KK*2048 total
    int p = idx & 2047;
    int m = p * 2;
    int r = idx >> 11;
    int kk = r % KK;
    int b = r / KK;
    int ci = kk & 255;
    int tap = kk >> 8;
    int y = (m >> 6) + tap / 3 - 1;
    int x0 = (m & 63) + tap % 3 - 1;
    float v0 = 0.f, v1 = 0.f;
    if ((unsigned)y < 64u) {
        const float* row = in + ((size_t)(b * CC + ci) * 64 + y) * 64;
        if ((unsigned)x0 < 64u) v0 = row[x0];
        if ((unsigned)(x0 + 1) < 64u) v1 = row[x0 + 1];
    }
    *(__half2*)(cols + ((size_t)(b * KK + kk)) * HW + m) =
        __floats2half2_rn(v0, v1);
}

// ---------------- deform sampling, merged cls+reg (z=8), 2 m per thread ----
__global__ void deform_h(const float* __restrict__ cls_feat,
                         const float* __restrict__ reg_feat,
                         const float* __restrict__ pts,
                         __half* __restrict__ cols) {
    int t = blockIdx.x * 256 + threadIdx.x;       // 0..2047
    int k = blockIdx.y, bb = blockIdx.z;
    const float* img = (bb < 4) ? cls_feat : reg_feat;
    int b = bb & 3;
    int m0 = t * 2;
    float bx = (float)(k - 4);
    int i00[2], i01[2], i10[2], i11[2];
    float w00[2], w01[2], w10[2], w11[2];
#pragma unroll
    for (int e = 0; e < 2; e++) {
        int m = m0 + e;
        int y = m >> 6, x = m & 63;
        float pty = pts[(b * 18 + 2 * k) * HW + m];
        float ptx = pts[(b * 18 + 2 * k + 1) * HW + m];
        float py = pty + (float)y;
        float px = ((ptx - bx) + (float)x) + bx;
        float y0f = floorf(py), x0f = floorf(px);
        int y0 = (int)y0f, x0 = (int)x0f;
        float wy = py - y0f, wx = px - x0f;
        float a00 = (1.f - wy) * (1.f - wx);
        float a01 = (1.f - wy) * wx;
        float a10 = wy * (1.f - wx);
        float a11 = wy * wx;
        bool vy0 = (y0 >= 0) && (y0 <= 63);
        bool vy1 = (y0 + 1 >= 0) && (y0 + 1 <= 63);
        bool vx0 = (x0 >= 0) && (x0 <= 63);
        bool vx1 = (x0 + 1 >= 0) && (x0 + 1 <= 63);
        w00[e] = (vy0 && vx0) ? a00 : 0.f;
        w01[e] = (vy0 && vx1) ? a01 : 0.f;
        w10[e] = (vy1 && vx0) ? a10 : 0.f;
        w11[e] = (vy1 && vx1) ? a11 : 0.f;
        int y0c = min(max(y0, 0), 63), y1c = min(max(y0 + 1, 0), 63);
        int x0c = min(max(x0, 0), 63), x1c = min(max(x0 + 1, 0), 63);
        i00[e] = y0c * 64 + x0c; i01[e] = y0c * 64 + x1c;
        i10[e] = y1c * 64 + x0c; i11[e] = y1c * 64 + x1c;
    }
    const float* ib = img + (size_t)b * CC * HW;
    __half* cb = cols + ((size_t)bb * KK + (size_t)k * CC) * HW + m0;
#pragma unroll 2
    for (int c = 0; c < CC; c++) {
        const float* ic = ib + (size_t)c * HW;
        float v0 = w00[0] * __ldg(ic + i00[0]) + w01[0] * __ldg(ic + i01[0])
                 + w10[0] * __ldg(ic + i10[0]) + w11[0] * __ldg(ic + i11[0]);
        float v1 = w00[1] * __ldg(ic + i00[1]) + w01[1] * __ldg(ic + i01[1])
                 + w10[1] * __ldg(ic + i10[1]) + w11[1] * __ldg(ic + i11[1]);
        *(__half2*)(cb + (size_t)c * HW) = __floats2half2_rn(v0, v1);
    }
}

// ---------------- GN finalize from atomic sums ----------------
__global__ void gn_finalize(int base, int count) {
    int i = threadIdx.x;
    if (i >= count) return;
    const float inv_n = 1.f / (float)(CPG * HW);
    float mean = g_statS[base + i] * inv_n;
    float var = g_statQ[base + i] * inv_n - mean * mean;
    g_mu[base + i] = mean;
    g_rstd[base + i] = rsqrtf(var + 1e-5f);
}

// ---------------- GN apply + ReLU, merged (covers 8 slots) ----------------
__global__ void gn_apply8(const float* __restrict__ raw,
                          const float* __restrict__ cls_g,
                          const float* __restrict__ cls_bt,
                          const float* __restrict__ reg_g,
                          const float* __restrict__ reg_bt,
                          float* __restrict__ out8) {
    int i = blockIdx.x * 256 + threadIdx.x;       // 8*CC*HW threads
    int c = (i >> 12) & 255;
    int bb = i >> 20;
    int sidx = 128 + (i >> 15);                   // 128 + bb*32 + (c>>3)
    const float* gamma = (bb < 4) ? cls_g : reg_g;
    const float* beta = (bb < 4) ? cls_bt : reg_bt;
    float v = (raw[i] - g_mu[sidx]) * g_rstd[sidx] * gamma[c] + beta[c];
    out8[i] = fmaxf(v, 0.f);
}

// ---------------- direct fp32 conv2 (GN+ReLU fused on input) ---------------
__global__ void __launch_bounds__(512, 1)
conv2_direct(const float* __restrict__ raw, const float* __restrict__ gamma,
             const float* __restrict__ beta, const float* __restrict__ w,
             const float* __restrict__ bias, float* __restrict__ pts) {
    __shared__ float win[4][2][4][64];
    __shared__ float ws[4][2][162];
    __shared__ float red[3][18][128];
    int b = blockIdx.z;
    int r0 = blockIdx.x * 2;
    int tid = threadIdx.x;
    int q = tid >> 7, t2 = tid & 127;
    int jb = t2 >> 6;
    int px = t2 & 63;

    float acc[18];
#pragma unroll
    for (int o = 0; o < 18; o++) acc[o] = 0.f;

    for (int c0 = 0; c0 < 64; c0 += 2) {
        __syncthreads();
#pragma unroll
        for (int e = t2; e < 512; e += 128) {
            int ch = e >> 8, j = (e >> 6) & 3, x = e & 63;
            int ci = q * 64 + c0 + ch;
            float grs = g_rstd[b * NG + (ci >> 3)];
            float gg = gamma[ci] * grs;
            float gb = beta[ci] - g_mu[b * NG + (ci >> 3)] * gg;
            int yy = r0 - 1 + j;
            float v = 0.f;
            if ((unsigned)yy < 64u)
                v = fmaxf(raw[(size_t)(b * CC + ci) * HW + yy * 64 + x] * gg + gb, 0.f);
            win[q][ch][j][x] = v;
        }
#pragma unroll
        for (int e = t2; e < 324; e += 128) {
            int ch = e / 162, r9 = e % 162;
            int ci = q * 64 + c0 + ch;
            ws[q][ch][r9] = w[((r9 / 9) * CC + ci) * 9 + (r9 % 9)];
        }
        __syncthreads();
#pragma unroll
        for (int ch = 0; ch < 2; ch++) {
            float v[9];
#pragma unroll
            for (int ky = 0; ky < 3; ky++)
#pragma unroll
                for (int kx = 0; kx < 3; kx++) {
                    int xx = px - 1 + kx;
                    v[ky * 3 + kx] = ((unsigned)xx < 64u) ? win[q][ch][jb + ky][xx] : 0.f;
                }
#pragma unroll
            for (int o = 0; o < 18; o++) {
                float s = acc[o];
#pragma unroll
                for (int t = 0; t < 9; t++) s += ws[q][ch][o * 9 + t] * v[t];
                acc[o] = s;
            }
        }
    }

    if (q > 0) {
#pragma unroll
        for (int o = 0; o < 18; o++) red[q - 1][o][t2] = acc[o];
    }
    __syncthreads();
    if (q == 0) {
        int yy = r0 + jb;
#pragma unroll
        for (int o = 0; o < 18; o++) {
            float s = acc[o] + red[0][o][t2] + red[1][o][t2] + red[2][o][t2] + bias[o];
            pts[((size_t)(b * 18 + o)) * HW + yy * 64 + px] = s;
        }
    }
}

// ---------------- fp16 mma.sync GEMM + fused GN partial stats --------------
// C[bb][n][m] = sum_kk A[bb][kk][m] * Bw[kk][n]; BM=128, BN=128, BK=16.
// Bw selected per bb (Bw1 for bb>=4). Stats atomically accumulated per group.
__global__ void __launch_bounds__(128, 2)
tgemm_h(const __half* __restrict__ A, const __half* __restrict__ Bw0,
        const __half* __restrict__ Bw1, float* __restrict__ Cout,
        const float* __restrict__ bias, int statBase) {
    __shared__ __align__(16) __half As[3][16 * 128];
    __shared__ __align__(16) __half Bs[3][16 * 128];
    __shared__ float sS[128], sQ[128];
    int bm = blockIdx.x * 128, bn = blockIdx.y * 128, bb = blockIdx.z;
    const __half* Ab = A + (size_t)bb * KK * HW + bm;
    const __half* Bb = ((bb < 4) ? Bw0 : Bw1) + bn;
    int tid = threadIdx.x;
    int warp = tid >> 5, lane = tid & 31;
    int wm = (warp & 1) * 64, wn = (warp >> 1) * 64;
    int r = lane >> 2, c = lane & 3;

    float acc[4][8][4];
#pragma unroll
    for (int mt = 0; mt < 4; mt++)
#pragma unroll
        for (int nt = 0; nt < 8; nt++)
#pragma unroll
            for (int i = 0; i < 4; i++) acc[mt][nt][i] = 0.f;

    int kA = (lane & 7) | ((lane & 16) >> 1);
    int cA = (lane & 8) >> 3;
    int kB = (lane & 7) | (lane & 8);
    int cB = (lane & 16) >> 4;
    uint32_t aOff[4], bOff[4];
#pragma unroll
    for (int mt = 0; mt < 4; mt++) {
        int chunk = (wm >> 3) + mt * 2 + cA;
        aOff[mt] = kA * 256 + ((chunk ^ (kA & 7)) << 4);
    }
#pragma unroll
    for (int p = 0; p < 4; p++) {
        int chunk = (wn >> 3) + p * 2 + cB;
        bOff[p] = kB * 256 + ((chunk ^ (kB & 7)) << 4);
    }

    auto stage = [&](int k0, int buf) {
#pragma unroll
        for (int s = 0; s < 2; s++) {
            int e = tid + s * 128;
            int k = e >> 4, cq = e & 15;
            uint32_t swz = (uint32_t)((cq ^ (k & 7)) << 4) + k * 256;
            cp16(smem_u32(&As[buf][0]) + swz, Ab + (size_t)(k0 + k) * HW + cq * 8);
            cp16(smem_u32(&Bs[buf][0]) + swz, Bb + (size_t)(k0 + k) * 256 + cq * 8);
        }
    };

    stage(0, 0); cp_commit();
    stage(16, 1); cp_commit();

    int buf = 0;
    for (int cc = 0; cc < NCHB; cc++) {
        if (cc + 2 < NCHB) stage((cc + 2) * 16, (cc + 2) % 3);
        cp_commit();
        cp_wait2();
        __syncthreads();
        uint32_t baseA = smem_u32(&As[buf][0]);
        uint32_t baseB = smem_u32(&Bs[buf][0]);
        uint32_t a[4][4], bq[4][4];
#pragma unroll
        for (int mt = 0; mt < 4; mt++) ldsm4t(a[mt], baseA + aOff[mt]);
#pragma unroll
        for (int p = 0; p < 4; p++) ldsm4t(bq[p], baseB + bOff[p]);
#pragma unroll
        for (int mt = 0; mt < 4; mt++)
#pragma unroll
            for (int nt = 0; nt < 8; nt++)
                mma16816(acc[mt][nt], a[mt], bq[nt >> 1][(nt & 1) * 2],
                         bq[nt >> 1][(nt & 1) * 2 + 1]);
        __syncthreads();
        buf = (buf == 2) ? 0 : buf + 1;
    }

    // add bias in-place (stats must include it)
    if (bias) {
#pragma unroll
        for (int nt = 0; nt < 8; nt++) {
            int n = bn + wn + nt * 8 + 2 * c;
            float b0 = bias[n], b1 = bias[n + 1];
#pragma unroll
            for (int mt = 0; mt < 4; mt++) {
                acc[mt][nt][0] += b0; acc[mt][nt][2] += b0;
                acc[mt][nt][1] += b1; acc[mt][nt][3] += b1;
            }
        }
    }

    // fused GN partial stats
    if (tid < 128) { sS[tid] = 0.f; sQ[tid] = 0.f; }
    __syncthreads();
#pragma unroll
    for (int nt = 0; nt < 8; nt++)
#pragma unroll
        for (int par = 0; par < 2; par++) {
            float sv = 0.f, sq = 0.f;
#pragma unroll
            for (int mt = 0; mt < 4; mt++) {
                float a0 = acc[mt][nt][par];
                float a1 = acc[mt][nt][par + 2];
                sv += a0 + a1;
                sq += a0 * a0 + a1 * a1;
            }
            int nl = wn + nt * 8 + 2 * c + par;
            atomicAdd(&sS[nl], sv);
            atomicAdd(&sQ[nl], sq);
        }
    __syncthreads();
    if (tid < 128) {
        int slot = statBase + bb * 32 + ((bn + tid) >> 3);
        atomicAdd(&g_statS[slot], sS[tid]);
        atomicAdd(&g_statQ[slot], sQ[tid]);
    }

    // store C
    float* Cb = Cout + (size_t)bb * (CC * HW);
#pragma unroll
    for (int mt = 0; mt < 4; mt++) {
        int m = bm + wm + mt * 16 + r;
#pragma unroll
        for (int nt = 0; nt < 8; nt++) {
            int n = bn + wn + nt * 8 + 2 * c;
            Cb[(size_t)n * HW + m]           = acc[mt][nt][0];
            Cb[(size_t)n * HW + m + 8]       = acc[mt][nt][2];
            Cb[(size_t)(n + 1) * HW + m]     = acc[mt][nt][1];
            Cb[(size_t)(n + 1) * HW + m + 8] = acc[mt][nt][3];
        }
    }
}

// ---------------- launch ----------------------------------------------------
extern "C" void kernel_launch(void* const* d_in, const int* in_sizes, int n_in,
                              void* d_out, int out_size) {
    const float* cls_feat = (const float*)d_in[0];
    const float* reg_feat = (const float*)d_in[1];
    const float* offc_w   = (const float*)d_in[2];
    const float* offc_b   = (const float*)d_in[3];
    const float* offc_g   = (const float*)d_in[4];
    const float* offc_bt  = (const float*)d_in[5];
    const float* offo_w   = (const float*)d_in[6];
    const float* offo_b   = (const float*)d_in[7];
    const float* clsdc_w  = (const float*)d_in[8];
    const float* cls_g    = (const float*)d_in[9];
    const float* cls_bt   = (const float*)d_in[10];
    const float* regdc_w  = (const float*)d_in[11];
    const float* reg_g    = (const float*)d_in[12];
    const float* reg_bt   = (const float*)d_in[13];

    float* out = (float*)d_out;
    float* pts = out;                          // [4][18][4096]
    float* out8 = out + (size_t)BB * 18 * HW;  // cls_out(4) then reg_out(4), contiguous

    float* raw;
    __half *cols, *wT1, *wTc, *wTr;
    cudaGetSymbolAddress((void**)&cols, g_cols);
    cudaGetSymbolAddress((void**)&raw, g_raw);
    cudaGetSymbolAddress((void**)&wT1, g_wT1);
    cudaGetSymbolAddress((void**)&wTc, g_wTc);
    cudaGetSymbolAddress((void**)&wTr, g_wTr);

    cudaStream_t s1 = g_sh.s1;

    const int colsBlocks = (BB * KK * 2048) / 256;
    const dim3 gBig4(32, 2, 4);
    const dim3 gBig8(32, 2, 8);
    const dim3 gDef(8, K9, 8);
    const dim3 gC2(32, 1, 4);

    // ---- fork: zero stats + weight transposes on s1, concurrent with im2col
    cudaEventRecord(g_sh.eF, 0);
    cudaStreamWaitEvent(s1, g_sh.eF, 0);
    zero_stats<<<1, 384, 0, s1>>>();
    transpose_all_h<<<(3 * KK * 256) / 256, 256, 0, s1>>>(offc_w, clsdc_w, regdc_w,
                                                          wT1, wTc, wTr);
    cudaEventRecord(g_sh.eT, s1);

    im2col_h<<<colsBlocks, 256>>>(reg_feat, cols);
    cudaStreamWaitEvent(0, g_sh.eT, 0);

    // ---- offset branch: conv1(+stats) -> finalize -> direct conv2 -> pts ----
    tgemm_h<<<gBig4, 128>>>(cols, wT1, wT1, raw, offc_b, 0);
    gn_finalize<<<1, 128>>>(0, 128);
    conv2_direct<<<gC2, 512>>>(raw, offc_g, offc_bt, offo_w, offo_b, pts);

    // ---- merged cls+reg: deform(z=8) -> gemm(z=8,+stats) -> finalize -> apply
    deform_h<<<gDef, 256>>>(cls_feat, reg_feat, pts, cols);
    tgemm_h<<<gBig8, 128>>>(cols, wTc, wTr, raw, nullptr, 128);
    gn_finalize<<<1, 256>>>(128, 256);
    gn_apply8<<<(8 * CC * HW) / 256, 256>>>(raw, cls_g, cls_bt, reg_g, reg_bt, out8);
}

// round 11
// speedup vs baseline: 1.0005x; 1.0005x over previous
#include <cuda_runtime.h>
#include <cuda_fp16.h>
#include <math.h>
#include <stdint.h>

#define BB 4
#define CC 256
#define HW 4096
#define K9 9
#define KK 2304   // 256*9
#define NG 32
#define CPG 8
#define NCHB 144  // KK/16 k-blocks

// ---------------- static scratch ----------------
__device__ __align__(16) __half g_cols[(size_t)8 * KK * HW];   // fp16 cols, [bb][kk][m], bb<4=cls, >=4=reg
__device__ float g_raw[(size_t)8 * CC * HW];                   // GEMM outputs (slot 0..3 reused by conv1)
__device__ __align__(16) __half g_wT1[KK * 256];               // [kk][o]
__device__ __align__(16) __half g_wTc[KK * 256];
__device__ __align__(16) __half g_wTr[KK * 256];
__device__ float g_statS[384];                                 // atomic GN sums: [0..127] conv1, [128..383] merged
__device__ float g_statQ[384];
__device__ float g_mu[384];
__device__ float g_rstd[384];

// ---------------- streams / events ----------------
struct StreamHolder {
    cudaStream_t s1;
    cudaEvent_t eF, eT;
    StreamHolder() {
        if (cudaStreamCreateWithFlags(&s1, cudaStreamNonBlocking) != cudaSuccess) s1 = 0;
        cudaEventCreateWithFlags(&eF, cudaEventDisableTiming);
        cudaEventCreateWithFlags(&eT, cudaEventDisableTiming);
    }
};
static StreamHolder g_sh;

// ---------------- helpers ----------------
__device__ __forceinline__ uint32_t smem_u32(const void* p) {
    uint32_t a;
    asm("{ .reg .u64 t; cvta.to.shared.u64 t, %1; cvt.u32.u64 %0, t; }"
        : "=r"(a) : "l"(p));
    return a;
}
__device__ __forceinline__ void cp16(uint32_t dst, const void* src) {
    asm volatile("cp.async.cg.shared.global [%0], [%1], 16;"
                 :: "r"(dst), "l"(src) : "memory");
}
__device__ __forceinline__ void cp_commit() {
    asm volatile("cp.async.commit_group;" ::: "memory");
}
__device__ __forceinline__ void cp_wait2() {
    asm volatile("cp.async.wait_group 2;" ::: "memory");
}
__device__ __forceinline__ void ldsm4t(uint32_t* d, uint32_t addr) {
    asm volatile("ldmatrix.sync.aligned.m8n8.x4.trans.shared.b16 {%0,%1,%2,%3}, [%4];"
        : "=r"(d[0]), "=r"(d[1]), "=r"(d[2]), "=r"(d[3]) : "r"(addr));
}
__device__ __forceinline__ void mma16816(float* d, const uint32_t* a,
                                         uint32_t b0, uint32_t b1) {
    asm volatile(
        "mma.sync.aligned.m16n8k16.row.col.f32.f16.f16.f32 "
        "{%0,%1,%2,%3},{%4,%5,%6,%7},{%8,%9},{%0,%1,%2,%3};"
        : "+f"(d[0]), "+f"(d[1]), "+f"(d[2]), "+f"(d[3])
        : "r"(a[0]), "r"(a[1]), "r"(a[2]), "r"(a[3]), "r"(b0), "r"(b1));
}

// ---------------- zero stat accumulators ----------------
__global__ void zero_stats() {
    int t = threadIdx.x;
    if (t < 384) { g_statS[t] = 0.f; g_statQ[t] = 0.f; }
}

// ---------------- weight transpose -> fp16: wT[kk][o] ----------------------
__global__ void transpose_all_h(const float* __restrict__ w1, const float* __restrict__ wc,
                                const float* __restrict__ wr,
                                __half* __restrict__ o1, __half* __restrict__ oc,
                                __half* __restrict__ orr) {
    const int S = KK * 256;
    int i = blockIdx.x * 256 + threadIdx.x;
    const float* w; __half* o; int j;
    if (i < S)          { w = w1; o = o1;  j = i; }
    else if (i < 2 * S) { w = wc; o = oc;  j = i - S; }
    else                { w = wr; o = orr; j = i - 2 * S; }
    int oo = j & 255;
    int kk = j >> 8;
    int ci = kk & 255;
    int tap = kk >> 8;
    o[j] = __float2half_rn(w[(oo * CC + ci) * K9 + tap]);
}

// ---------------- im2col 3x3 pad1 -> fp16 cols[b][kk][m], 2 m per thread ----
__global__ void im2col_h(const float* __restrict__ in, __half* __restrict__ cols) {
    int idx = blockIdx.x * 256 + threadIdx.x;     // BB*KK*2048 total
    int p = idx & 2047;
    int m = p * 2;
    int r = idx >> 11;
    int kk = r % KK;
    int b = r / KK;
    int ci = kk & 255;
    int tap = kk >> 8;
    int y = (m >> 6) + tap / 3 - 1;
    int x0 = (m & 63) + tap % 3 - 1;
    float v0 = 0.f, v1 = 0.f;
    if ((unsigned)y < 64u) {
        const float* row = in + ((size_t)(b * CC + ci) * 64 + y) * 64;
        if ((unsigned)x0 < 64u) v0 = row[x0];
        if ((unsigned)(x0 + 1) < 64u) v1 = row[x0 + 1];
    }
    *(__half2*)(cols + ((size_t)(b * KK + kk)) * HW + m) =
        __floats2half2_rn(v0, v1);
}

// ---------------- deform sampling, merged cls+reg (z=8), 2 m per thread ----
__global__ void deform_h(const float* __restrict__ cls_feat,
                         const float* __restrict__ reg_feat,
                         const float* __restrict__ pts,
                         __half* __restrict__ cols) {
    int t = blockIdx.x * 256 + threadIdx.x;       // 0..2047
    int k = blockIdx.y, bb = blockIdx.z;
    const float* img = (bb < 4) ? cls_feat : reg_feat;
    int b = bb & 3;
    int m0 = t * 2;
    float bx = (float)(k - 4);
    int i00[2], i01[2], i10[2], i11[2];
    float w00[2], w01[2], w10[2], w11[2];
#pragma unroll
    for (int e = 0; e < 2; e++) {
        int m = m0 + e;
        int y = m >> 6, x = m & 63;
        float pty = pts[(b * 18 + 2 * k) * HW + m];
        float ptx = pts[(b * 18 + 2 * k + 1) * HW + m];
        float py = pty + (float)y;
        float px = ((ptx - bx) + (float)x) + bx;
        float y0f = floorf(py), x0f = floorf(px);
        int y0 = (int)y0f, x0 = (int)x0f;
        float wy = py - y0f, wx = px - x0f;
        float a00 = (1.f - wy) * (1.f - wx);
        float a01 = (1.f - wy) * wx;
        float a10 = wy * (1.f - wx);
        float a11 = wy * wx;
        bool vy0 = (y0 >= 0) && (y0 <= 63);
        bool vy1 = (y0 + 1 >= 0) && (y0 + 1 <= 63);
        bool vx0 = (x0 >= 0) && (x0 <= 63);
        bool vx1 = (x0 + 1 >= 0) && (x0 + 1 <= 63);
        w00[e] = (vy0 && vx0) ? a00 : 0.f;
        w01[e] = (vy0 && vx1) ? a01 : 0.f;
        w10[e] = (vy1 && vx0) ? a10 : 0.f;
        w11[e] = (vy1 && vx1) ? a11 : 0.f;
        int y0c = min(max(y0, 0), 63), y1c = min(max(y0 + 1, 0), 63);
        int x0c = min(max(x0, 0), 63), x1c = min(max(x0 + 1, 0), 63);
        i00[e] = y0c * 64 + x0c; i01[e] = y0c * 64 + x1c;
        i10[e] = y1c * 64 + x0c; i11[e] = y1c * 64 + x1c;
    }
    const float* ib = img + (size_t)b * CC * HW;
    __half* cb = cols + ((size_t)bb * KK + (size_t)k * CC) * HW + m0;
#pragma unroll 2
    for (int c = 0; c < CC; c++) {
        const float* ic = ib + (size_t)c * HW;
        float v0 = w00[0] * __ldg(ic + i00[0]) + w01[0] * __ldg(ic + i01[0])
                 + w10[0] * __ldg(ic + i10[0]) + w11[0] * __ldg(ic + i11[0]);
        float v1 = w00[1] * __ldg(ic + i00[1]) + w01[1] * __ldg(ic + i01[1])
                 + w10[1] * __ldg(ic + i10[1]) + w11[1] * __ldg(ic + i11[1]);
        *(__half2*)(cb + (size_t)c * HW) = __floats2half2_rn(v0, v1);
    }
}

// ---------------- GN finalize from atomic sums ----------------
__global__ void gn_finalize(int base, int count) {
    int i = threadIdx.x;
    if (i >= count) return;
    const float inv_n = 1.f / (float)(CPG * HW);
    float mean = g_statS[base + i] * inv_n;
    float var = g_statQ[base + i] * inv_n - mean * mean;
    g_mu[base + i] = mean;
    g_rstd[base + i] = rsqrtf(var + 1e-5f);
}

// ---------------- GN apply + ReLU, merged (covers 8 slots) ----------------
__global__ void gn_apply8(const float* __restrict__ raw,
                          const float* __restrict__ cls_g,
                          const float* __restrict__ cls_bt,
                          const float* __restrict__ reg_g,
                          const float* __restrict__ reg_bt,
                          float* __restrict__ out8) {
    int i = blockIdx.x * 256 + threadIdx.x;       // 8*CC*HW threads
    int c = (i >> 12) & 255;
    int bb = i >> 20;
    int sidx = 128 + (i >> 15);                   // 128 + bb*32 + (c>>3)
    const float* gamma = (bb < 4) ? cls_g : reg_g;
    const float* beta = (bb < 4) ? cls_bt : reg_bt;
    float v = (raw[i] - g_mu[sidx]) * g_rstd[sidx] * gamma[c] + beta[c];
    out8[i] = fmaxf(v, 0.f);
}

// ---------------- direct fp32 conv2 (GN+ReLU fused on input) ---------------
__global__ void __launch_bounds__(512, 1)
conv2_direct(const float* __restrict__ raw, const float* __restrict__ gamma,
             const float* __restrict__ beta, const float* __restrict__ w,
             const float* __restrict__ bias, float* __restrict__ pts) {
    __shared__ float win[4][2][4][64];
    __shared__ float ws[4][2][162];
    __shared__ float red[3][18][128];
    int b = blockIdx.z;
    int r0 = blockIdx.x * 2;
    int tid = threadIdx.x;
    int q = tid >> 7, t2 = tid & 127;
    int jb = t2 >> 6;
    int px = t2 & 63;

    float acc[18];
#pragma unroll
    for (int o = 0; o < 18; o++) acc[o] = 0.f;

    for (int c0 = 0; c0 < 64; c0 += 2) {
        __syncthreads();
#pragma unroll
        for (int e = t2; e < 512; e += 128) {
            int ch = e >> 8, j = (e >> 6) & 3, x = e & 63;
            int ci = q * 64 + c0 + ch;
            float grs = g_rstd[b * NG + (ci >> 3)];
            float gg = gamma[ci] * grs;
            float gb = beta[ci] - g_mu[b * NG + (ci >> 3)] * gg;
            int yy = r0 - 1 + j;
            float v = 0.f;
            if ((unsigned)yy < 64u)
                v = fmaxf(raw[(size_t)(b * CC + ci) * HW + yy * 64 + x] * gg + gb, 0.f);
            win[q][ch][j][x] = v;
        }
#pragma unroll
        for (int e = t2; e < 324; e += 128) {
            int ch = e / 162, r9 = e % 162;
            int ci = q * 64 + c0 + ch;
            ws[q][ch][r9] = w[((r9 / 9) * CC + ci) * 9 + (r9 % 9)];
        }
        __syncthreads();
#pragma unroll
        for (int ch = 0; ch < 2; ch++) {
            float v[9];
#pragma unroll
            for (int ky = 0; ky < 3; ky++)
#pragma unroll
                for (int kx = 0; kx < 3; kx++) {
                    int xx = px - 1 + kx;
                    v[ky * 3 + kx] = ((unsigned)xx < 64u) ? win[q][ch][jb + ky][xx] : 0.f;
                }
#pragma unroll
            for (int o = 0; o < 18; o++) {
                float s = acc[o];
#pragma unroll
                for (int t = 0; t < 9; t++) s += ws[q][ch][o * 9 + t] * v[t];
                acc[o] = s;
            }
        }
    }

    if (q > 0) {
#pragma unroll
        for (int o = 0; o < 18; o++) red[q - 1][o][t2] = acc[o];
    }
    __syncthreads();
    if (q == 0) {
        int yy = r0 + jb;
#pragma unroll
        for (int o = 0; o < 18; o++) {
            float s = acc[o] + red[0][o][t2] + red[1][o][t2] + red[2][o][t2] + bias[o];
            pts[((size_t)(b * 18 + o)) * HW + yy * 64 + px] = s;
        }
    }
}

// ---------------- fp16 mma.sync GEMM + fused GN partial stats --------------
// C[bb][n][m] = sum_kk A[bb][kk][m] * Bw[kk][n]; BM=128, BN=128, BK=16.
// Bw selected per bb (Bw1 for bb>=4). Stats atomically accumulated per group.
__global__ void __launch_bounds__(128, 2)
tgemm_h(const __half* __restrict__ A, const __half* __restrict__ Bw0,
        const __half* __restrict__ Bw1, float* __restrict__ Cout,
        const float* __restrict__ bias, int statBase) {
    __shared__ __align__(16) __half As[3][16 * 128];
    __shared__ __align__(16) __half Bs[3][16 * 128];
    __shared__ float sS[128], sQ[128];
    int bm = blockIdx.x * 128, bn = blockIdx.y * 128, bb = blockIdx.z;
    const __half* Ab = A + (size_t)bb * KK * HW + bm;
    const __half* Bb = ((bb < 4) ? Bw0 : Bw1) + bn;
    int tid = threadIdx.x;
    int warp = tid >> 5, lane = tid & 31;
    int wm = (warp & 1) * 64, wn = (warp >> 1) * 64;
    int r = lane >> 2, c = lane & 3;

    float acc[4][8][4];
#pragma unroll
    for (int mt = 0; mt < 4; mt++)
#pragma unroll
        for (int nt = 0; nt < 8; nt++)
#pragma unroll
            for (int i = 0; i < 4; i++) acc[mt][nt][i] = 0.f;

    int kA = (lane & 7) | ((lane & 16) >> 1);
    int cA = (lane & 8) >> 3;
    int kB = (lane & 7) | (lane & 8);
    int cB = (lane & 16) >> 4;
    uint32_t aOff[4], bOff[4];
#pragma unroll
    for (int mt = 0; mt < 4; mt++) {
        int chunk = (wm >> 3) + mt * 2 + cA;
        aOff[mt] = kA * 256 + ((chunk ^ (kA & 7)) << 4);
    }
#pragma unroll
    for (int p = 0; p < 4; p++) {
        int chunk = (wn >> 3) + p * 2 + cB;
        bOff[p] = kB * 256 + ((chunk ^ (kB & 7)) << 4);
    }

    auto stage = [&](int k0, int buf) {
#pragma unroll
        for (int s = 0; s < 2; s++) {
            int e = tid + s * 128;
            int k = e >> 4, cq = e & 15;
            uint32_t swz = (uint32_t)((cq ^ (k & 7)) << 4) + k * 256;
            cp16(smem_u32(&As[buf][0]) + swz, Ab + (size_t)(k0 + k) * HW + cq * 8);
            cp16(smem_u32(&Bs[buf][0]) + swz, Bb + (size_t)(k0 + k) * 256 + cq * 8);
        }
    };

    stage(0, 0); cp_commit();
    stage(16, 1); cp_commit();

    int buf = 0;
    for (int cc = 0; cc < NCHB; cc++) {
        if (cc + 2 < NCHB) stage((cc + 2) * 16, (cc + 2) % 3);
        cp_commit();
        cp_wait2();
        __syncthreads();
        uint32_t baseA = smem_u32(&As[buf][0]);
        uint32_t baseB = smem_u32(&Bs[buf][0]);
        uint32_t a[4][4], bq[4][4];
#pragma unroll
        for (int mt = 0; mt < 4; mt++) ldsm4t(a[mt], baseA + aOff[mt]);
#pragma unroll
        for (int p = 0; p < 4; p++) ldsm4t(bq[p], baseB + bOff[p]);
#pragma unroll
        for (int mt = 0; mt < 4; mt++)
#pragma unroll
            for (int nt = 0; nt < 8; nt++)
                mma16816(acc[mt][nt], a[mt], bq[nt >> 1][(nt & 1) * 2],
                         bq[nt >> 1][(nt & 1) * 2 + 1]);
        __syncthreads();
        buf = (buf == 2) ? 0 : buf + 1;
    }

    // add bias in-place (stats must include it)
    if (bias) {
#pragma unroll
        for (int nt = 0; nt < 8; nt++) {
            int n = bn + wn + nt * 8 + 2 * c;
            float b0 = bias[n], b1 = bias[n + 1];
#pragma unroll
            for (int mt = 0; mt < 4; mt++) {
                acc[mt][nt][0] += b0; acc[mt][nt][2] += b0;
                acc[mt][nt][1] += b1; acc[mt][nt][3] += b1;
            }
        }
    }

    // fused GN partial stats
    if (tid < 128) { sS[tid] = 0.f; sQ[tid] = 0.f; }
    __syncthreads();
#pragma unroll
    for (int nt = 0; nt < 8; nt++)
#pragma unroll
        for (int par = 0; par < 2; par++) {
            float sv = 0.f, sq = 0.f;
#pragma unroll
            for (int mt = 0; mt < 4; mt++) {
                float a0 = acc[mt][nt][par];
                float a1 = acc[mt][nt][par + 2];
                sv += a0 + a1;
                sq += a0 * a0 + a1 * a1;
            }
            int nl = wn + nt * 8 + 2 * c + par;
            atomicAdd(&sS[nl], sv);
            atomicAdd(&sQ[nl], sq);
        }
    __syncthreads();
    if (tid < 128) {
        int slot = statBase + bb * 32 + ((bn + tid) >> 3);
        atomicAdd(&g_statS[slot], sS[tid]);
        atomicAdd(&g_statQ[slot], sQ[tid]);
    }

    // store C
    float* Cb = Cout + (size_t)bb * (CC * HW);
#pragma unroll
    for (int mt = 0; mt < 4; mt++) {
        int m = bm + wm + mt * 16 + r;
#pragma unroll
        for (int nt = 0; nt < 8; nt++) {
            int n = bn + wn + nt * 8 + 2 * c;
            Cb[(size_t)n * HW + m]           = acc[mt][nt][0];
            Cb[(size_t)n * HW + m + 8]       = acc[mt][nt][2];
            Cb[(size_t)(n + 1) * HW + m]     = acc[mt][nt][1];
            Cb[(size_t)(n + 1) * HW + m + 8] = acc[mt][nt][3];
        }
    }
}

// ---------------- launch ----------------------------------------------------
extern "C" void kernel_launch(void* const* d_in, const int* in_sizes, int n_in,
                              void* d_out, int out_size) {
    const float* cls_feat = (const float*)d_in[0];
    const float* reg_feat = (const float*)d_in[1];
    const float* offc_w   = (const float*)d_in[2];
    const float* offc_b   = (const float*)d_in[3];
    const float* offc_g   = (const float*)d_in[4];
    const float* offc_bt  = (const float*)d_in[5];
    const float* offo_w   = (const float*)d_in[6];
    const float* offo_b   = (const float*)d_in[7];
    const float* clsdc_w  = (const float*)d_in[8];
    const float* cls_g    = (const float*)d_in[9];
    const float* cls_bt   = (const float*)d_in[10];
    const float* regdc_w  = (const float*)d_in[11];
    const float* reg_g    = (const float*)d_in[12];
    const float* reg_bt   = (const float*)d_in[13];

    float* out = (float*)d_out;
    float* pts = out;                          // [4][18][4096]
    float* out8 = out + (size_t)BB * 18 * HW;  // cls_out(4) then reg_out(4), contiguous

    float* raw;
    __half *cols, *wT1, *wTc, *wTr;
    cudaGetSymbolAddress((void**)&cols, g_cols);
    cudaGetSymbolAddress((void**)&raw, g_raw);
    cudaGetSymbolAddress((void**)&wT1, g_wT1);
    cudaGetSymbolAddress((void**)&wTc, g_wTc);
    cudaGetSymbolAddress((void**)&wTr, g_wTr);

    cudaStream_t s1 = g_sh.s1;

    const int colsBlocks = (BB * KK * 2048) / 256;
    const dim3 gBig4(32, 2, 4);
    const dim3 gBig8(32, 2, 8);
    const dim3 gDef(8, K9, 8);
    const dim3 gC2(32, 1, 4);

    // ---- fork: zero stats + weight transposes on s1, concurrent with im2col
    cudaEventRecord(g_sh.eF, 0);
    cudaStreamWaitEvent(s1, g_sh.eF, 0);
    zero_stats<<<1, 384, 0, s1>>>();
    transpose_all_h<<<(3 * KK * 256) / 256, 256, 0, s1>>>(offc_w, clsdc_w, regdc_w,
                                                          wT1, wTc, wTr);
    cudaEventRecord(g_sh.eT, s1);

    im2col_h<<<colsBlocks, 256>>>(reg_feat, cols);
    cudaStreamWaitEvent(0, g_sh.eT, 0);

    // ---- offset branch: conv1(+stats) -> finalize -> direct conv2 -> pts ----
    tgemm_h<<<gBig4, 128>>>(cols, wT1, wT1, raw, offc_b, 0);
    gn_finalize<<<1, 128>>>(0, 128);
    conv2_direct<<<gC2, 512>>>(raw, offc_g, offc_bt, offo_w, offo_b, pts);

    // ---- merged cls+reg: deform(z=8) -> gemm(z=8,+stats) -> finalize -> apply
    deform_h<<<gDef, 256>>>(cls_feat, reg_feat, pts, cols);
    tgemm_h<<<gBig8, 128>>>(cols, wTc, wTr, raw, nullptr, 128);
    gn_finalize<<<1, 256>>>(128, 256);
    gn_apply8<<<(8 * CC * HW) / 256, 256>>>(raw, cls_g, cls_bt, reg_g, reg_bt, out8);
}

// round 12
// speedup vs baseline: 1.0009x; 1.0005x over previous
#include <cuda_runtime.h>
#include <cuda_fp16.h>
#include <math.h>
#include <stdint.h>

#define BB 4
#define CC 256
#define HW 4096
#define K9 9
#define KK 2304   // 256*9
#define NG 32
#define CPG 8
#define NCHB 144  // KK/16 k-blocks

// ---------------- static scratch ----------------
__device__ __align__(16) __half g_cols[(size_t)8 * KK * HW];   // fp16 cols, [bb][kk][m], bb<4=cls, >=4=reg
__device__ float g_raw[(size_t)8 * CC * HW];                   // GEMM outputs (slot 0..3 reused by conv1)
__device__ __align__(16) __half g_wT1[KK * 256];               // [kk][o]
__device__ __align__(16) __half g_wTc[KK * 256];
__device__ __align__(16) __half g_wTr[KK * 256];
__device__ float g_statS[384];                                 // atomic GN sums: [0..127] conv1, [128..383] merged
__device__ float g_statQ[384];
__device__ float g_mu[384];
__device__ float g_rstd[384];

// ---------------- streams / events ----------------
struct StreamHolder {
    cudaStream_t s1;
    cudaEvent_t eF, eT;
    StreamHolder() {
        if (cudaStreamCreateWithFlags(&s1, cudaStreamNonBlocking) != cudaSuccess) s1 = 0;
        cudaEventCreateWithFlags(&eF, cudaEventDisableTiming);
        cudaEventCreateWithFlags(&eT, cudaEventDisableTiming);
    }
};
static StreamHolder g_sh;

// ---------------- helpers ----------------
__device__ __forceinline__ uint32_t smem_u32(const void* p) {
    uint32_t a;
    asm("{ .reg .u64 t; cvta.to.shared.u64 t, %1; cvt.u32.u64 %0, t; }"
        : "=r"(a) : "l"(p));
    return a;
}
__device__ __forceinline__ void cp16(uint32_t dst, const void* src) {
    asm volatile("cp.async.cg.shared.global [%0], [%1], 16;"
                 :: "r"(dst), "l"(src) : "memory");
}
__device__ __forceinline__ void cp_commit() {
    asm volatile("cp.async.commit_group;" ::: "memory");
}
__device__ __forceinline__ void cp_wait2() {
    asm volatile("cp.async.wait_group 2;" ::: "memory");
}
__device__ __forceinline__ void ldsm4t(uint32_t* d, uint32_t addr) {
    asm volatile("ldmatrix.sync.aligned.m8n8.x4.trans.shared.b16 {%0,%1,%2,%3}, [%4];"
        : "=r"(d[0]), "=r"(d[1]), "=r"(d[2]), "=r"(d[3]) : "r"(addr));
}
__device__ __forceinline__ void mma16816(float* d, const uint32_t* a,
                                         uint32_t b0, uint32_t b1) {
    asm volatile(
        "mma.sync.aligned.m16n8k16.row.col.f32.f16.f16.f32 "
        "{%0,%1,%2,%3},{%4,%5,%6,%7},{%8,%9},{%0,%1,%2,%3};"
        : "+f"(d[0]), "+f"(d[1]), "+f"(d[2]), "+f"(d[3])
        : "r"(a[0]), "r"(a[1]), "r"(a[2]), "r"(a[3]), "r"(b0), "r"(b1));
}

// ---------------- zero stat accumulators ----------------
__global__ void zero_stats() {
    int t = threadIdx.x;
    if (t < 384) { g_statS[t] = 0.f; g_statQ[t] = 0.f; }
}

// ---------------- weight transpose -> fp16: wT[kk][o] ----------------------
__global__ void transpose_all_h(const float* __restrict__ w1, const float* __restrict__ wc,
                                const float* __restrict__ wr,
                                __half* __restrict__ o1, __half* __restrict__ oc,
                                __half* __restrict__ orr) {
    const int S = KK * 256;
    int i = blockIdx.x * 256 + threadIdx.x;
    const float* w; __half* o; int j;
    if (i < S)          { w = w1; o = o1;  j = i; }
    else if (i < 2 * S) { w = wc; o = oc;  j = i - S; }
    else                { w = wr; o = orr; j = i - 2 * S; }
    int oo = j & 255;
    int kk = j >> 8;
    int ci = kk & 255;
    int tap = kk >> 8;
    o[j] = __float2half_rn(w[(oo * CC + ci) * K9 + tap]);
}

// ---------------- im2col 3x3 pad1 -> fp16 cols[b][kk][m], 2 m per thread ----
__global__ void im2col_h(const float* __restrict__ in, __half* __restrict__ cols) {
    int idx = blockIdx.x * 256 + threadIdx.x;     // BB*KK*2048 total
    int p = idx & 2047;
    int m = p * 2;
    int r = idx >> 11;
    int kk = r % KK;
    int b = r / KK;
    int ci = kk & 255;
    int tap = kk >> 8;
    int y = (m >> 6) + tap / 3 - 1;
    int x0 = (m & 63) + tap % 3 - 1;
    float v0 = 0.f, v1 = 0.f;
    if ((unsigned)y < 64u) {
        const float* row = in + ((size_t)(b * CC + ci) * 64 + y) * 64;
        if ((unsigned)x0 < 64u) v0 = row[x0];
        if ((unsigned)(x0 + 1) < 64u) v1 = row[x0 + 1];
    }
    *(__half2*)(cols + ((size_t)(b * KK + kk)) * HW + m) =
        __floats2half2_rn(v0, v1);
}

// ---------------- deform sampling, merged cls+reg (z=8), 2 m per thread ----
__global__ void deform_h(const float* __restrict__ cls_feat,
                         const float* __restrict__ reg_feat,
                         const float* __restrict__ pts,
                         __half* __restrict__ cols) {
    int t = blockIdx.x * 256 + threadIdx.x;       // 0..2047
    int k = blockIdx.y, bb = blockIdx.z;
    const float* img = (bb < 4) ? cls_feat : reg_feat;
    int b = bb & 3;
    int m0 = t * 2;
    float bx = (float)(k - 4);
    int i00[2], i01[2], i10[2], i11[2];
    float w00[2], w01[2], w10[2], w11[2];
#pragma unroll
    for (int e = 0; e < 2; e++) {
        int m = m0 + e;
        int y = m >> 6, x = m & 63;
        float pty = pts[(b * 18 + 2 * k) * HW + m];
        float ptx = pts[(b * 18 + 2 * k + 1) * HW + m];
        float py = pty + (float)y;
        float px = ((ptx - bx) + (float)x) + bx;
        float y0f = floorf(py), x0f = floorf(px);
        int y0 = (int)y0f, x0 = (int)x0f;
        float wy = py - y0f, wx = px - x0f;
        float a00 = (1.f - wy) * (1.f - wx);
        float a01 = (1.f - wy) * wx;
        float a10 = wy * (1.f - wx);
        float a11 = wy * wx;
        bool vy0 = (y0 >= 0) && (y0 <= 63);
        bool vy1 = (y0 + 1 >= 0) && (y0 + 1 <= 63);
        bool vx0 = (x0 >= 0) && (x0 <= 63);
        bool vx1 = (x0 + 1 >= 0) && (x0 + 1 <= 63);
        w00[e] = (vy0 && vx0) ? a00 : 0.f;
        w01[e] = (vy0 && vx1) ? a01 : 0.f;
        w10[e] = (vy1 && vx0) ? a10 : 0.f;
        w11[e] = (vy1 && vx1) ? a11 : 0.f;
        int y0c = min(max(y0, 0), 63), y1c = min(max(y0 + 1, 0), 63);
        int x0c = min(max(x0, 0), 63), x1c = min(max(x0 + 1, 0), 63);
        i00[e] = y0c * 64 + x0c; i01[e] = y0c * 64 + x1c;
        i10[e] = y1c * 64 + x0c; i11[e] = y1c * 64 + x1c;
    }
    const float* ib = img + (size_t)b * CC * HW;
    __half* cb = cols + ((size_t)bb * KK + (size_t)k * CC) * HW + m0;
#pragma unroll 2
    for (int c = 0; c < CC; c++) {
        const float* ic = ib + (size_t)c * HW;
        float v0 = w00[0] * __ldg(ic + i00[0]) + w01[0] * __ldg(ic + i01[0])
                 + w10[0] * __ldg(ic + i10[0]) + w11[0] * __ldg(ic + i11[0]);
        float v1 = w00[1] * __ldg(ic + i00[1]) + w01[1] * __ldg(ic + i01[1])
                 + w10[1] * __ldg(ic + i10[1]) + w11[1] * __ldg(ic + i11[1]);
        *(__half2*)(cb + (size_t)c * HW) = __floats2half2_rn(v0, v1);
    }
}

// ---------------- GN finalize from atomic sums ----------------
__global__ void gn_finalize(int base, int count) {
    int i = threadIdx.x;
    if (i >= count) return;
    const float inv_n = 1.f / (float)(CPG * HW);
    float mean = g_statS[base + i] * inv_n;
    float var = g_statQ[base + i] * inv_n - mean * mean;
    g_mu[base + i] = mean;
    g_rstd[base + i] = rsqrtf(var + 1e-5f);
}

// ---------------- GN apply + ReLU, merged (covers 8 slots) ----------------
__global__ void gn_apply8(const float* __restrict__ raw,
                          const float* __restrict__ cls_g,
                          const float* __restrict__ cls_bt,
                          const float* __restrict__ reg_g,
                          const float* __restrict__ reg_bt,
                          float* __restrict__ out8) {
    int i = blockIdx.x * 256 + threadIdx.x;       // 8*CC*HW threads
    int c = (i >> 12) & 255;
    int bb = i >> 20;
    int sidx = 128 + (i >> 15);                   // 128 + bb*32 + (c>>3)
    const float* gamma = (bb < 4) ? cls_g : reg_g;
    const float* beta = (bb < 4) ? cls_bt : reg_bt;
    float v = (raw[i] - g_mu[sidx]) * g_rstd[sidx] * gamma[c] + beta[c];
    out8[i] = fmaxf(v, 0.f);
}

// ---------------- direct fp32 conv2 (GN+ReLU fused on input) ---------------
__global__ void __launch_bounds__(512, 1)
conv2_direct(const float* __restrict__ raw, const float* __restrict__ gamma,
             const float* __restrict__ beta, const float* __restrict__ w,
             const float* __restrict__ bias, float* __restrict__ pts) {
    __shared__ float win[4][2][4][64];
    __shared__ float ws[4][2][162];
    __shared__ float red[3][18][128];
    int b = blockIdx.z;
    int r0 = blockIdx.x * 2;
    int tid = threadIdx.x;
    int q = tid >> 7, t2 = tid & 127;
    int jb = t2 >> 6;
    int px = t2 & 63;

    float acc[18];
#pragma unroll
    for (int o = 0; o < 18; o++) acc[o] = 0.f;

    for (int c0 = 0; c0 < 64; c0 += 2) {
        __syncthreads();
#pragma unroll
        for (int e = t2; e < 512; e += 128) {
            int ch = e >> 8, j = (e >> 6) & 3, x = e & 63;
            int ci = q * 64 + c0 + ch;
            float grs = g_rstd[b * NG + (ci >> 3)];
            float gg = gamma[ci] * grs;
            float gb = beta[ci] - g_mu[b * NG + (ci >> 3)] * gg;
            int yy = r0 - 1 + j;
            float v = 0.f;
            if ((unsigned)yy < 64u)
                v = fmaxf(raw[(size_t)(b * CC + ci) * HW + yy * 64 + x] * gg + gb, 0.f);
            win[q][ch][j][x] = v;
        }
#pragma unroll
        for (int e = t2; e < 324; e += 128) {
            int ch = e / 162, r9 = e % 162;
            int ci = q * 64 + c0 + ch;
            ws[q][ch][r9] = w[((r9 / 9) * CC + ci) * 9 + (r9 % 9)];
        }
        __syncthreads();
#pragma unroll
        for (int ch = 0; ch < 2; ch++) {
            float v[9];
#pragma unroll
            for (int ky = 0; ky < 3; ky++)
#pragma unroll
                for (int kx = 0; kx < 3; kx++) {
                    int xx = px - 1 + kx;
                    v[ky * 3 + kx] = ((unsigned)xx < 64u) ? win[q][ch][jb + ky][xx] : 0.f;
                }
#pragma unroll
            for (int o = 0; o < 18; o++) {
                float s = acc[o];
#pragma unroll
                for (int t = 0; t < 9; t++) s += ws[q][ch][o * 9 + t] * v[t];
                acc[o] = s;
            }
        }
    }

    if (q > 0) {
#pragma unroll
        for (int o = 0; o < 18; o++) red[q - 1][o][t2] = acc[o];
    }
    __syncthreads();
    if (q == 0) {
        int yy = r0 + jb;
#pragma unroll
        for (int o = 0; o < 18; o++) {
            float s = acc[o] + red[0][o][t2] + red[1][o][t2] + red[2][o][t2] + bias[o];
            pts[((size_t)(b * 18 + o)) * HW + yy * 64 + px] = s;
        }
    }
}

// ---------------- fp16 mma.sync GEMM + fused GN partial stats --------------
// C[bb][n][m] = sum_kk A[bb][kk][m] * Bw[kk][n]; BM=128, BN=128, BK=16.
// Bw selected per bb (Bw1 for bb>=4). Stats atomically accumulated per group.
__global__ void __launch_bounds__(128, 2)
tgemm_h(const __half* __restrict__ A, const __half* __restrict__ Bw0,
        const __half* __restrict__ Bw1, float* __restrict__ Cout,
        const float* __restrict__ bias, int statBase) {
    __shared__ __align__(16) __half As[3][16 * 128];
    __shared__ __align__(16) __half Bs[3][16 * 128];
    __shared__ float sS[128], sQ[128];
    int bm = blockIdx.x * 128, bn = blockIdx.y * 128, bb = blockIdx.z;
    const __half* Ab = A + (size_t)bb * KK * HW + bm;
    const __half* Bb = ((bb < 4) ? Bw0 : Bw1) + bn;
    int tid = threadIdx.x;
    int warp = tid >> 5, lane = tid & 31;
    int wm = (warp & 1) * 64, wn = (warp >> 1) * 64;
    int r = lane >> 2, c = lane & 3;

    float acc[4][8][4];
#pragma unroll
    for (int mt = 0; mt < 4; mt++)
#pragma unroll
        for (int nt = 0; nt < 8; nt++)
#pragma unroll
            for (int i = 0; i < 4; i++) acc[mt][nt][i] = 0.f;

    int kA = (lane & 7) | ((lane & 16) >> 1);
    int cA = (lane & 8) >> 3;
    int kB = (lane & 7) | (lane & 8);
    int cB = (lane & 16) >> 4;
    uint32_t aOff[4], bOff[4];
#pragma unroll
    for (int mt = 0; mt < 4; mt++) {
        int chunk = (wm >> 3) + mt * 2 + cA;
        aOff[mt] = kA * 256 + ((chunk ^ (kA & 7)) << 4);
    }
#pragma unroll
    for (int p = 0; p < 4; p++) {
        int chunk = (wn >> 3) + p * 2 + cB;
        bOff[p] = kB * 256 + ((chunk ^ (kB & 7)) << 4);
    }

    auto stage = [&](int k0, int buf) {
#pragma unroll
        for (int s = 0; s < 2; s++) {
            int e = tid + s * 128;
            int k = e >> 4, cq = e & 15;
            uint32_t swz = (uint32_t)((cq ^ (k & 7)) << 4) + k * 256;
            cp16(smem_u32(&As[buf][0]) + swz, Ab + (size_t)(k0 + k) * HW + cq * 8);
            cp16(smem_u32(&Bs[buf][0]) + swz, Bb + (size_t)(k0 + k) * 256 + cq * 8);
        }
    };

    stage(0, 0); cp_commit();
    stage(16, 1); cp_commit();

    int buf = 0;
    for (int cc = 0; cc < NCHB; cc++) {
        if (cc + 2 < NCHB) stage((cc + 2) * 16, (cc + 2) % 3);
        cp_commit();
        cp_wait2();
        __syncthreads();
        uint32_t baseA = smem_u32(&As[buf][0]);
        uint32_t baseB = smem_u32(&Bs[buf][0]);
        uint32_t a[4][4], bq[4][4];
#pragma unroll
        for (int mt = 0; mt < 4; mt++) ldsm4t(a[mt], baseA + aOff[mt]);
#pragma unroll
        for (int p = 0; p < 4; p++) ldsm4t(bq[p], baseB + bOff[p]);
#pragma unroll
        for (int mt = 0; mt < 4; mt++)
#pragma unroll
            for (int nt = 0; nt < 8; nt++)
                mma16816(acc[mt][nt], a[mt], bq[nt >> 1][(nt & 1) * 2],
                         bq[nt >> 1][(nt & 1) * 2 + 1]);
        __syncthreads();
        buf = (buf == 2) ? 0 : buf + 1;
    }

    // add bias in-place (stats must include it)
    if (bias) {
#pragma unroll
        for (int nt = 0; nt < 8; nt++) {
            int n = bn + wn + nt * 8 + 2 * c;
            float b0 = bias[n], b1 = bias[n + 1];
#pragma unroll
            for (int mt = 0; mt < 4; mt++) {
                acc[mt][nt][0] += b0; acc[mt][nt][2] += b0;
                acc[mt][nt][1] += b1; acc[mt][nt][3] += b1;
            }
        }
    }

    // fused GN partial stats
    if (tid < 128) { sS[tid] = 0.f; sQ[tid] = 0.f; }
    __syncthreads();
#pragma unroll
    for (int nt = 0; nt < 8; nt++)
#pragma unroll
        for (int par = 0; par < 2; par++) {
            float sv = 0.f, sq = 0.f;
#pragma unroll
            for (int mt = 0; mt < 4; mt++) {
                float a0 = acc[mt][nt][par];
                float a1 = acc[mt][nt][par + 2];
                sv += a0 + a1;
                sq += a0 * a0 + a1 * a1;
            }
            int nl = wn + nt * 8 + 2 * c + par;
            atomicAdd(&sS[nl], sv);
            atomicAdd(&sQ[nl], sq);
        }
    __syncthreads();
    if (tid < 128) {
        int slot = statBase + bb * 32 + ((bn + tid) >> 3);
        atomicAdd(&g_statS[slot], sS[tid]);
        atomicAdd(&g_statQ[slot], sQ[tid]);
    }

    // store C
    float* Cb = Cout + (size_t)bb * (CC * HW);
#pragma unroll
    for (int mt = 0; mt < 4; mt++) {
        int m = bm + wm + mt * 16 + r;
#pragma unroll
        for (int nt = 0; nt < 8; nt++) {
            int n = bn + wn + nt * 8 + 2 * c;
            Cb[(size_t)n * HW + m]           = acc[mt][nt][0];
            Cb[(size_t)n * HW + m + 8]       = acc[mt][nt][2];
            Cb[(size_t)(n + 1) * HW + m]     = acc[mt][nt][1];
            Cb[(size_t)(n + 1) * HW + m + 8] = acc[mt][nt][3];
        }
    }
}

// ---------------- launch ----------------------------------------------------
extern "C" void kernel_launch(void* const* d_in, const int* in_sizes, int n_in,
                              void* d_out, int out_size) {
    const float* cls_feat = (const float*)d_in[0];
    const float* reg_feat = (const float*)d_in[1];
    const float* offc_w   = (const float*)d_in[2];
    const float* offc_b   = (const float*)d_in[3];
    const float* offc_g   = (const float*)d_in[4];
    const float* offc_bt  = (const float*)d_in[5];
    const float* offo_w   = (const float*)d_in[6];
    const float* offo_b   = (const float*)d_in[7];
    const float* clsdc_w  = (const float*)d_in[8];
    const float* cls_g    = (const float*)d_in[9];
    const float* cls_bt   = (const float*)d_in[10];
    const float* regdc_w  = (const float*)d_in[11];
    const float* reg_g    = (const float*)d_in[12];
    const float* reg_bt   = (const float*)d_in[13];

    float* out = (float*)d_out;
    float* pts = out;                          // [4][18][4096]
    float* out8 = out + (size_t)BB * 18 * HW;  // cls_out(4) then reg_out(4), contiguous

    float* raw;
    __half *cols, *wT1, *wTc, *wTr;
    cudaGetSymbolAddress((void**)&cols, g_cols);
    cudaGetSymbolAddress((void**)&raw, g_raw);
    cudaGetSymbolAddress((void**)&wT1, g_wT1);
    cudaGetSymbolAddress((void**)&wTc, g_wTc);
    cudaGetSymbolAddress((void**)&wTr, g_wTr);

    cudaStream_t s1 = g_sh.s1;

    const int colsBlocks = (BB * KK * 2048) / 256;
    const dim3 gBig4(32, 2, 4);
    const dim3 gBig8(32, 2, 8);
    const dim3 gDef(8, K9, 8);
    const dim3 gC2(32, 1, 4);

    // ---- fork: zero stats + weight transposes on s1, concurrent with im2col
    cudaEventRecord(g_sh.eF, 0);
    cudaStreamWaitEvent(s1, g_sh.eF, 0);
    zero_stats<<<1, 384, 0, s1>>>();
    transpose_all_h<<<(3 * KK * 256) / 256, 256, 0, s1>>>(offc_w, clsdc_w, regdc_w,
                                                          wT1, wTc, wTr);
    cudaEventRecord(g_sh.eT, s1);

    im2col_h<<<colsBlocks, 256>>>(reg_feat, cols);
    cudaStreamWaitEvent(0, g_sh.eT, 0);

    // ---- offset branch: conv1(+stats) -> finalize -> direct conv2 -> pts ----
    tgemm_h<<<gBig4, 128>>>(cols, wT1, wT1, raw, offc_b, 0);
    gn_finalize<<<1, 128>>>(0, 128);
    conv2_direct<<<gC2, 512>>>(raw, offc_g, offc_bt, offo_w, offo_b, pts);

    // ---- merged cls+reg: deform(z=8) -> gemm(z=8,+stats) -> finalize -> apply
    deform_h<<<gDef, 256>>>(cls_feat, reg_feat, pts, cols);
    tgemm_h<<<gBig8, 128>>>(cols, wTc, wTr, raw, nullptr, 128);
    gn_finalize<<<1, 256>>>(128, 256);
    gn_apply8<<<(8 * CC * HW) / 256, 256>>>(raw, cls_g, cls_bt, reg_g, reg_bt, out8);
}

// round 13
// speedup vs baseline: 1.0031x; 1.0022x over previous
#include <cuda_runtime.h>
#include <cuda_fp16.h>
#include <math.h>
#include <stdint.h>

#define BB 4
#define CC 256
#define HW 4096
#define K9 9
#define KK 2304   // 256*9
#define NG 32
#define CPG 8
#define NCHB 144  // KK/16 k-blocks

// ---------------- static scratch ----------------
__device__ __align__(16) __half g_cols[(size_t)8 * KK * HW];   // fp16 cols, [bb][kk][m], bb<4=cls, >=4=reg
__device__ float g_raw[(size_t)8 * CC * HW];                   // GEMM outputs (slot 0..3 reused by conv1)
__device__ __align__(16) __half g_wT1[KK * 256];               // [kk][o]
__device__ __align__(16) __half g_wTc[KK * 256];
__device__ __align__(16) __half g_wTr[KK * 256];
__device__ float g_statS[384];                                 // atomic GN sums: [0..127] conv1, [128..383] merged
__device__ float g_statQ[384];
__device__ float g_mu[384];
__device__ float g_rstd[384];

// ---------------- streams / events ----------------
struct StreamHolder {
    cudaStream_t s1;
    cudaEvent_t eF, eT;
    StreamHolder() {
        if (cudaStreamCreateWithFlags(&s1, cudaStreamNonBlocking) != cudaSuccess) s1 = 0;
        cudaEventCreateWithFlags(&eF, cudaEventDisableTiming);
        cudaEventCreateWithFlags(&eT, cudaEventDisableTiming);
    }
};
static StreamHolder g_sh;

// ---------------- helpers ----------------
__device__ __forceinline__ uint32_t smem_u32(const void* p) {
    uint32_t a;
    asm("{ .reg .u64 t; cvta.to.shared.u64 t, %1; cvt.u32.u64 %0, t; }"
        : "=r"(a) : "l"(p));
    return a;
}
__device__ __forceinline__ void cp16(uint32_t dst, const void* src) {
    asm volatile("cp.async.cg.shared.global [%0], [%1], 16;"
                 :: "r"(dst), "l"(src) : "memory");
}
__device__ __forceinline__ void cp_commit() {
    asm volatile("cp.async.commit_group;" ::: "memory");
}
__device__ __forceinline__ void cp_wait2() {
    asm volatile("cp.async.wait_group 2;" ::: "memory");
}
__device__ __forceinline__ void ldsm4t(uint32_t* d, uint32_t addr) {
    asm volatile("ldmatrix.sync.aligned.m8n8.x4.trans.shared.b16 {%0,%1,%2,%3}, [%4];"
        : "=r"(d[0]), "=r"(d[1]), "=r"(d[2]), "=r"(d[3]) : "r"(addr));
}
__device__ __forceinline__ void mma16816(float* d, const uint32_t* a,
                                         uint32_t b0, uint32_t b1) {
    asm volatile(
        "mma.sync.aligned.m16n8k16.row.col.f32.f16.f16.f32 "
        "{%0,%1,%2,%3},{%4,%5,%6,%7},{%8,%9},{%0,%1,%2,%3};"
        : "+f"(d[0]), "+f"(d[1]), "+f"(d[2]), "+f"(d[3])
        : "r"(a[0]), "r"(a[1]), "r"(a[2]), "r"(a[3]), "r"(b0), "r"(b1));
}

// ---------------- zero stat accumulators ----------------
__global__ void zero_stats() {
    int t = threadIdx.x;
    if (t < 384) { g_statS[t] = 0.f; g_statQ[t] = 0.f; }
}

// ---------------- weight transpose -> fp16: wT[kk][o] ----------------------
__global__ void transpose_all_h(const float* __restrict__ w1, const float* __restrict__ wc,
                                const float* __restrict__ wr,
                                __half* __restrict__ o1, __half* __restrict__ oc,
                                __half* __restrict__ orr) {
    const int S = KK * 256;
    int i = blockIdx.x * 256 + threadIdx.x;
    const float* w; __half* o; int j;
    if (i < S)          { w = w1; o = o1;  j = i; }
    else if (i < 2 * S) { w = wc; o = oc;  j = i - S; }
    else                { w = wr; o = orr; j = i - 2 * S; }
    int oo = j & 255;
    int kk = j >> 8;
    int ci = kk & 255;
    int tap = kk >> 8;
    o[j] = __float2half_rn(w[(oo * CC + ci) * K9 + tap]);
}

// ---------------- im2col 3x3 pad1 -> fp16 cols[b][kk][m], 2 m per thread ----
__global__ void im2col_h(const float* __restrict__ in, __half* __restrict__ cols) {
    int idx = blockIdx.x * 256 + threadIdx.x;     // BB*KK*2048 total
    int p = idx & 2047;
    int m = p * 2;
    int r = idx >> 11;
    int kk = r % KK;
    int b = r / KK;
    int ci = kk & 255;
    int tap = kk >> 8;
    int y = (m >> 6) + tap / 3 - 1;
    int x0 = (m & 63) + tap % 3 - 1;
    float v0 = 0.f, v1 = 0.f;
    if ((unsigned)y < 64u) {
        const float* row = in + ((size_t)(b * CC + ci) * 64 + y) * 64;
        if ((unsigned)x0 < 64u) v0 = row[x0];
        if ((unsigned)(x0 + 1) < 64u) v1 = row[x0 + 1];
    }
    *(__half2*)(cols + ((size_t)(b * KK + kk)) * HW + m) =
        __floats2half2_rn(v0, v1);
}

// ---------------- deform sampling, merged cls+reg (z=8), 2 m per thread ----
__global__ void deform_h(const float* __restrict__ cls_feat,
                         const float* __restrict__ reg_feat,
                         const float* __restrict__ pts,
                         __half* __restrict__ cols) {
    int t = blockIdx.x * 256 + threadIdx.x;       // 0..2047
    int k = blockIdx.y, bb = blockIdx.z;
    const float* img = (bb < 4) ? cls_feat : reg_feat;
    int b = bb & 3;
    int m0 = t * 2;
    float bx = (float)(k - 4);
    int i00[2], i01[2], i10[2], i11[2];
    float w00[2], w01[2], w10[2], w11[2];
#pragma unroll
    for (int e = 0; e < 2; e++) {
        int m = m0 + e;
        int y = m >> 6, x = m & 63;
        float pty = pts[(b * 18 + 2 * k) * HW + m];
        float ptx = pts[(b * 18 + 2 * k + 1) * HW + m];
        float py = pty + (float)y;
        float px = ((ptx - bx) + (float)x) + bx;
        float y0f = floorf(py), x0f = floorf(px);
        int y0 = (int)y0f, x0 = (int)x0f;
        float wy = py - y0f, wx = px - x0f;
        float a00 = (1.f - wy) * (1.f - wx);
        float a01 = (1.f - wy) * wx;
        float a10 = wy * (1.f - wx);
        float a11 = wy * wx;
        bool vy0 = (y0 >= 0) && (y0 <= 63);
        bool vy1 = (y0 + 1 >= 0) && (y0 + 1 <= 63);
        bool vx0 = (x0 >= 0) && (x0 <= 63);
        bool vx1 = (x0 + 1 >= 0) && (x0 + 1 <= 63);
        w00[e] = (vy0 && vx0) ? a00 : 0.f;
        w01[e] = (vy0 && vx1) ? a01 : 0.f;
        w10[e] = (vy1 && vx0) ? a10 : 0.f;
        w11[e] = (vy1 && vx1) ? a11 : 0.f;
        int y0c = min(max(y0, 0), 63), y1c = min(max(y0 + 1, 0), 63);
        int x0c = min(max(x0, 0), 63), x1c = min(max(x0 + 1, 0), 63);
        i00[e] = y0c * 64 + x0c; i01[e] = y0c * 64 + x1c;
        i10[e] = y1c * 64 + x0c; i11[e] = y1c * 64 + x1c;
    }
    const float* ib = img + (size_t)b * CC * HW;
    __half* cb = cols + ((size_t)bb * KK + (size_t)k * CC) * HW + m0;
#pragma unroll 2
    for (int c = 0; c < CC; c++) {
        const float* ic = ib + (size_t)c * HW;
        float v0 = w00[0] * __ldg(ic + i00[0]) + w01[0] * __ldg(ic + i01[0])
                 + w10[0] * __ldg(ic + i10[0]) + w11[0] * __ldg(ic + i11[0]);
        float v1 = w00[1] * __ldg(ic + i00[1]) + w01[1] * __ldg(ic + i01[1])
                 + w10[1] * __ldg(ic + i10[1]) + w11[1] * __ldg(ic + i11[1]);
        *(__half2*)(cb + (size_t)c * HW) = __floats2half2_rn(v0, v1);
    }
}

// ---------------- GN finalize from atomic sums ----------------
__global__ void gn_finalize(int base, int count) {
    int i = threadIdx.x;
    if (i >= count) return;
    const float inv_n = 1.f / (float)(CPG * HW);
    float mean = g_statS[base + i] * inv_n;
    float var = g_statQ[base + i] * inv_n - mean * mean;
    g_mu[base + i] = mean;
    g_rstd[base + i] = rsqrtf(var + 1e-5f);
}

// ---------------- GN apply + ReLU, merged (covers 8 slots) ----------------
__global__ void gn_apply8(const float* __restrict__ raw,
                          const float* __restrict__ cls_g,
                          const float* __restrict__ cls_bt,
                          const float* __restrict__ reg_g,
                          const float* __restrict__ reg_bt,
                          float* __restrict__ out8) {
    int i = blockIdx.x * 256 + threadIdx.x;       // 8*CC*HW threads
    int c = (i >> 12) & 255;
    int bb = i >> 20;
    int sidx = 128 + (i >> 15);                   // 128 + bb*32 + (c>>3)
    const float* gamma = (bb < 4) ? cls_g : reg_g;
    const float* beta = (bb < 4) ? cls_bt : reg_bt;
    float v = (raw[i] - g_mu[sidx]) * g_rstd[sidx] * gamma[c] + beta[c];
    out8[i] = fmaxf(v, 0.f);
}

// ---------------- direct fp32 conv2 (GN+ReLU fused on input) ---------------
__global__ void __launch_bounds__(512, 1)
conv2_direct(const float* __restrict__ raw, const float* __restrict__ gamma,
             const float* __restrict__ beta, const float* __restrict__ w,
             const float* __restrict__ bias, float* __restrict__ pts) {
    __shared__ float win[4][2][4][64];
    __shared__ float ws[4][2][162];
    __shared__ float red[3][18][128];
    int b = blockIdx.z;
    int r0 = blockIdx.x * 2;
    int tid = threadIdx.x;
    int q = tid >> 7, t2 = tid & 127;
    int jb = t2 >> 6;
    int px = t2 & 63;

    float acc[18];
#pragma unroll
    for (int o = 0; o < 18; o++) acc[o] = 0.f;

    for (int c0 = 0; c0 < 64; c0 += 2) {
        __syncthreads();
#pragma unroll
        for (int e = t2; e < 512; e += 128) {
            int ch = e >> 8, j = (e >> 6) & 3, x = e & 63;
            int ci = q * 64 + c0 + ch;
            float grs = g_rstd[b * NG + (ci >> 3)];
            float gg = gamma[ci] * grs;
            float gb = beta[ci] - g_mu[b * NG + (ci >> 3)] * gg;
            int yy = r0 - 1 + j;
            float v = 0.f;
            if ((unsigned)yy < 64u)
                v = fmaxf(raw[(size_t)(b * CC + ci) * HW + yy * 64 + x] * gg + gb, 0.f);
            win[q][ch][j][x] = v;
        }
#pragma unroll
        for (int e = t2; e < 324; e += 128) {
            int ch = e / 162, r9 = e % 162;
            int ci = q * 64 + c0 + ch;
            ws[q][ch][r9] = w[((r9 / 9) * CC + ci) * 9 + (r9 % 9)];
        }
        __syncthreads();
#pragma unroll
        for (int ch = 0; ch < 2; ch++) {
            float v[9];
#pragma unroll
            for (int ky = 0; ky < 3; ky++)
#pragma unroll
                for (int kx = 0; kx < 3; kx++) {
                    int xx = px - 1 + kx;
                    v[ky * 3 + kx] = ((unsigned)xx < 64u) ? win[q][ch][jb + ky][xx] : 0.f;
                }
#pragma unroll
            for (int o = 0; o < 18; o++) {
                float s = acc[o];
#pragma unroll
                for (int t = 0; t < 9; t++) s += ws[q][ch][o * 9 + t] * v[t];
                acc[o] = s;
            }
        }
    }

    if (q > 0) {
#pragma unroll
        for (int o = 0; o < 18; o++) red[q - 1][o][t2] = acc[o];
    }
    __syncthreads();
    if (q == 0) {
        int yy = r0 + jb;
#pragma unroll
        for (int o = 0; o < 18; o++) {
            float s = acc[o] + red[0][o][t2] + red[1][o][t2] + red[2][o][t2] + bias[o];
            pts[((size_t)(b * 18 + o)) * HW + yy * 64 + px] = s;
        }
    }
}

// ---------------- fp16 mma.sync GEMM + fused GN partial stats --------------
// C[bb][n][m] = sum_kk A[bb][kk][m] * Bw[kk][n]; BM=128, BN=128, BK=16.
// Bw selected per bb (Bw1 for bb>=4). Stats atomically accumulated per group.
__global__ void __launch_bounds__(128, 2)
tgemm_h(const __half* __restrict__ A, const __half* __restrict__ Bw0,
        const __half* __restrict__ Bw1, float* __restrict__ Cout,
        const float* __restrict__ bias, int statBase) {
    __shared__ __align__(16) __half As[3][16 * 128];
    __shared__ __align__(16) __half Bs[3][16 * 128];
    __shared__ float sS[128], sQ[128];
    int bm = blockIdx.x * 128, bn = blockIdx.y * 128, bb = blockIdx.z;
    const __half* Ab = A + (size_t)bb * KK * HW + bm;
    const __half* Bb = ((bb < 4) ? Bw0 : Bw1) + bn;
    int tid = threadIdx.x;
    int warp = tid >> 5, lane = tid & 31;
    int wm = (warp & 1) * 64, wn = (warp >> 1) * 64;
    int r = lane >> 2, c = lane & 3;

    float acc[4][8][4];
#pragma unroll
    for (int mt = 0; mt < 4; mt++)
#pragma unroll
        for (int nt = 0; nt < 8; nt++)
#pragma unroll
            for (int i = 0; i < 4; i++) acc[mt][nt][i] = 0.f;

    int kA = (lane & 7) | ((lane & 16) >> 1);
    int cA = (lane & 8) >> 3;
    int kB = (lane & 7) | (lane & 8);
    int cB = (lane & 16) >> 4;
    uint32_t aOff[4], bOff[4];
#pragma unroll
    for (int mt = 0; mt < 4; mt++) {
        int chunk = (wm >> 3) + mt * 2 + cA;
        aOff[mt] = kA * 256 + ((chunk ^ (kA & 7)) << 4);
    }
#pragma unroll
    for (int p = 0; p < 4; p++) {
        int chunk = (wn >> 3) + p * 2 + cB;
        bOff[p] = kB * 256 + ((chunk ^ (kB & 7)) << 4);
    }

    auto stage = [&](int k0, int buf) {
#pragma unroll
        for (int s = 0; s < 2; s++) {
            int e = tid + s * 128;
            int k = e >> 4, cq = e & 15;
            uint32_t swz = (uint32_t)((cq ^ (k & 7)) << 4) + k * 256;
            cp16(smem_u32(&As[buf][0]) + swz, Ab + (size_t)(k0 + k) * HW + cq * 8);
            cp16(smem_u32(&Bs[buf][0]) + swz, Bb + (size_t)(k0 + k) * 256 + cq * 8);
        }
    };

    stage(0, 0); cp_commit();
    stage(16, 1); cp_commit();

    int buf = 0;
    for (int cc = 0; cc < NCHB; cc++) {
        if (cc + 2 < NCHB) stage((cc + 2) * 16, (cc + 2) % 3);
        cp_commit();
        cp_wait2();
        __syncthreads();
        uint32_t baseA = smem_u32(&As[buf][0]);
        uint32_t baseB = smem_u32(&Bs[buf][0]);
        uint32_t a[4][4], bq[4][4];
#pragma unroll
        for (int mt = 0; mt < 4; mt++) ldsm4t(a[mt], baseA + aOff[mt]);
#pragma unroll
        for (int p = 0; p < 4; p++) ldsm4t(bq[p], baseB + bOff[p]);
#pragma unroll
        for (int mt = 0; mt < 4; mt++)
#pragma unroll
            for (int nt = 0; nt < 8; nt++)
                mma16816(acc[mt][nt], a[mt], bq[nt >> 1][(nt & 1) * 2],
                         bq[nt >> 1][(nt & 1) * 2 + 1]);
        __syncthreads();
        buf = (buf == 2) ? 0 : buf + 1;
    }

    // add bias in-place (stats must include it)
    if (bias) {
#pragma unroll
        for (int nt = 0; nt < 8; nt++) {
            int n = bn + wn + nt * 8 + 2 * c;
            float b0 = bias[n], b1 = bias[n + 1];
#pragma unroll
            for (int mt = 0; mt < 4; mt++) {
                acc[mt][nt][0] += b0; acc[mt][nt][2] += b0;
                acc[mt][nt][1] += b1; acc[mt][nt][3] += b1;
            }
        }
    }

    // fused GN partial stats
    if (tid < 128) { sS[tid] = 0.f; sQ[tid] = 0.f; }
    __syncthreads();
#pragma unroll
    for (int nt = 0; nt < 8; nt++)
#pragma unroll
        for (int par = 0; par < 2; par++) {
            float sv = 0.f, sq = 0.f;
#pragma unroll
            for (int mt = 0; mt < 4; mt++) {
                float a0 = acc[mt][nt][par];
                float a1 = acc[mt][nt][par + 2];
                sv += a0 + a1;
                sq += a0 * a0 + a1 * a1;
            }
            int nl = wn + nt * 8 + 2 * c + par;
            atomicAdd(&sS[nl], sv);
            atomicAdd(&sQ[nl], sq);
        }
    __syncthreads();
    if (tid < 128) {
        int slot = statBase + bb * 32 + ((bn + tid) >> 3);
        atomicAdd(&g_statS[slot], sS[tid]);
        atomicAdd(&g_statQ[slot], sQ[tid]);
    }

    // store C
    float* Cb = Cout + (size_t)bb * (CC * HW);
#pragma unroll
    for (int mt = 0; mt < 4; mt++) {
        int m = bm + wm + mt * 16 + r;
#pragma unroll
        for (int nt = 0; nt < 8; nt++) {
            int n = bn + wn + nt * 8 + 2 * c;
            Cb[(size_t)n * HW + m]           = acc[mt][nt][0];
            Cb[(size_t)n * HW + m + 8]       = acc[mt][nt][2];
            Cb[(size_t)(n + 1) * HW + m]     = acc[mt][nt][1];
            Cb[(size_t)(n + 1) * HW + m + 8] = acc[mt][nt][3];
        }
    }
}

// ---------------- launch ----------------------------------------------------
extern "C" void kernel_launch(void* const* d_in, const int* in_sizes, int n_in,
                              void* d_out, int out_size) {
    const float* cls_feat = (const float*)d_in[0];
    const float* reg_feat = (const float*)d_in[1];
    const float* offc_w   = (const float*)d_in[2];
    const float* offc_b   = (const float*)d_in[3];
    const float* offc_g   = (const float*)d_in[4];
    const float* offc_bt  = (const float*)d_in[5];
    const float* offo_w   = (const float*)d_in[6];
    const float* offo_b   = (const float*)d_in[7];
    const float* clsdc_w  = (const float*)d_in[8];
    const float* cls_g    = (const float*)d_in[9];
    const float* cls_bt   = (const float*)d_in[10];
    const float* regdc_w  = (const float*)d_in[11];
    const float* reg_g    = (const float*)d_in[12];
    const float* reg_bt   = (const float*)d_in[13];

    float* out = (float*)d_out;
    float* pts = out;                          // [4][18][4096]
    float* out8 = out + (size_t)BB * 18 * HW;  // cls_out(4) then reg_out(4), contiguous

    float* raw;
    __half *cols, *wT1, *wTc, *wTr;
    cudaGetSymbolAddress((void**)&cols, g_cols);
    cudaGetSymbolAddress((void**)&raw, g_raw);
    cudaGetSymbolAddress((void**)&wT1, g_wT1);
    cudaGetSymbolAddress((void**)&wTc, g_wTc);
    cudaGetSymbolAddress((void**)&wTr, g_wTr);

    cudaStream_t s1 = g_sh.s1;

    const int colsBlocks = (BB * KK * 2048) / 256;
    const dim3 gBig4(32, 2, 4);
    const dim3 gBig8(32, 2, 8);
    const dim3 gDef(8, K9, 8);
    const dim3 gC2(32, 1, 4);

    // ---- fork: zero stats + weight transposes on s1, concurrent with im2col
    cudaEventRecord(g_sh.eF, 0);
    cudaStreamWaitEvent(s1, g_sh.eF, 0);
    zero_stats<<<1, 384, 0, s1>>>();
    transpose_all_h<<<(3 * KK * 256) / 256, 256, 0, s1>>>(offc_w, clsdc_w, regdc_w,
                                                          wT1, wTc, wTr);
    cudaEventRecord(g_sh.eT, s1);

    im2col_h<<<colsBlocks, 256>>>(reg_feat, cols);
    cudaStreamWaitEvent(0, g_sh.eT, 0);

    // ---- offset branch: conv1(+stats) -> finalize -> direct conv2 -> pts ----
    tgemm_h<<<gBig4, 128>>>(cols, wT1, wT1, raw, offc_b, 0);
    gn_finalize<<<1, 128>>>(0, 128);
    conv2_direct<<<gC2, 512>>>(raw, offc_g, offc_bt, offo_w, offo_b, pts);

    // ---- merged cls+reg: deform(z=8) -> gemm(z=8,+stats) -> finalize -> apply
    deform_h<<<gDef, 256>>>(cls_feat, reg_feat, pts, cols);
    tgemm_h<<<gBig8, 128>>>(cols, wTc, wTr, raw, nullptr, 128);
    gn_finalize<<<1, 256>>>(128, 256);
    gn_apply8<<<(8 * CC * HW) / 256, 256>>>(raw, cls_g, cls_bt, reg_g, reg_bt, out8);
}